// round 15
// baseline (speedup 1.0000x reference)
#include <cuda_runtime.h>
#include <cuda_bf16.h>
#include <cuda_fp16.h>
#include <cstdint>

#define S_LEN   4096
#define D_MODEL 1024
#define N_HEADS 16
#define HD      64
#define SCALE   0.125f
#define QALPHA  (0.125f * 1.44269504088896f)   // SCALE * log2(e)

// ---------------------------------------------------------------------------
// Scratch (device globals: allocation-free)
// ---------------------------------------------------------------------------
__device__ __align__(16) __half g_xf [S_LEN * D_MODEL];
__device__ __align__(16) __half g_qf [S_LEN * D_MODEL];
__device__ __align__(16) __half g_kf [S_LEN * D_MODEL];
__device__ __align__(16) __half g_vf [S_LEN * D_MODEL];
__device__ __align__(16) __half g_of [S_LEN * D_MODEL];
__device__ __align__(16) __half g_wqf[D_MODEL * D_MODEL];
__device__ __align__(16) __half g_wkf[D_MODEL * D_MODEL];
__device__ __align__(16) __half g_wvf[D_MODEL * D_MODEL];
__device__ __align__(16) __half g_wof[D_MODEL * D_MODEL];

// ---------------------------------------------------------------------------
// helpers
// ---------------------------------------------------------------------------
__device__ __forceinline__ uint32_t smem_u32(const void* p) {
    uint32_t a;
    asm("{ .reg .u64 t; cvta.to.shared.u64 t, %1; cvt.u32.u64 %0, t; }"
        : "=r"(a) : "l"(p));
    return a;
}

__device__ __forceinline__ void ldm_x4(uint32_t* r, uint32_t addr) {
    asm volatile("ldmatrix.sync.aligned.m8n8.x4.shared.b16 {%0,%1,%2,%3}, [%4];"
                 : "=r"(r[0]), "=r"(r[1]), "=r"(r[2]), "=r"(r[3]) : "r"(addr));
}
__device__ __forceinline__ void ldm_x4_t(uint32_t* r, uint32_t addr) {
    asm volatile("ldmatrix.sync.aligned.m8n8.x4.trans.shared.b16 {%0,%1,%2,%3}, [%4];"
                 : "=r"(r[0]), "=r"(r[1]), "=r"(r[2]), "=r"(r[3]) : "r"(addr));
}

__device__ __forceinline__ void mma_f16(float* c, const uint32_t* a,
                                        const uint32_t* b) {
    asm volatile(
        "mma.sync.aligned.m16n8k16.row.col.f32.f16.f16.f32 "
        "{%0,%1,%2,%3}, {%4,%5,%6,%7}, {%8,%9}, {%0,%1,%2,%3};"
        : "+f"(c[0]), "+f"(c[1]), "+f"(c[2]), "+f"(c[3])
        : "r"(a[0]), "r"(a[1]), "r"(a[2]), "r"(a[3]), "r"(b[0]), "r"(b[1]));
}

__device__ __forceinline__ uint32_t pack_h2(float x, float y) {
    __half2 h = __floats2half2_rn(x, y);
    return *(uint32_t*)&h;
}

__device__ __forceinline__ uint32_t h2exp2_u(uint32_t x) {
    uint32_t r;
    asm("ex2.approx.f16x2 %0, %1;" : "=r"(r) : "r"(x));
    return r;
}

#define CP_ASYNC16(saddr, gptr) \
    asm volatile("cp.async.cg.shared.global [%0], [%1], 16;" :: "r"(saddr), "l"(gptr))
#define CP_COMMIT() asm volatile("cp.async.commit_group;" ::: "memory")
#define CP_WAIT1()  asm volatile("cp.async.wait_group 1;" ::: "memory")

// ---------------------------------------------------------------------------
// fused fp32 -> fp16 convert for x (4 segs) + 4 weights. grid (1024, 8).
// ---------------------------------------------------------------------------
__global__ void conv_all(
    const float* __restrict__ x,  const float* __restrict__ Wq,
    const float* __restrict__ Wk, const float* __restrict__ Wv,
    const float* __restrict__ Wo,
    __half* __restrict__ xf,  __half* __restrict__ wqf,
    __half* __restrict__ wkf, __half* __restrict__ wvf,
    __half* __restrict__ wof)
{
    const int seg = blockIdx.y;
    const int SEG4 = D_MODEL * D_MODEL / 4;
    const float* src;
    __half* dst;
    int off = 0;
    if (seg < 4)      { src = x;  dst = xf;  off = seg * SEG4; }
    else if (seg == 4){ src = Wq; dst = wqf; }
    else if (seg == 5){ src = Wk; dst = wkf; }
    else if (seg == 6){ src = Wv; dst = wvf; }
    else              { src = Wo; dst = wof; }

    int i = off + blockIdx.x * blockDim.x + threadIdx.x;
    float4 v = ((const float4*)src)[i];
    ((uint32_t*)dst)[2*i]   = pack_h2(v.x, v.y);
    ((uint32_t*)dst)[2*i+1] = pack_h2(v.z, v.w);
}

// ---------------------------------------------------------------------------
// Pipelined fp16 HMMA GEMM core. C[M,N] = alpha * A[M,K] @ B[N,K]^T.
// 128x128 CTA tile, BK=64, 2-stage cp.async double buffer, 8 warps (4m x 2n),
// 2 CTAs/SM. 16 chunks of 64 MMAs each — big tensor batches per barrier pair.
// ---------------------------------------------------------------------------
#define TST     72                       // bf16 elems per smem row (144B)
#define ARR_B   (128 * TST * 2)          // 18432 B per array per stage
#define STAGE_B (2 * ARR_B)              // A + B = 36864
#define GEMM_SMEM (2 * STAGE_B)          // 73728

__device__ __forceinline__ void gemm_core_f16(
    const __half* __restrict__ A, const __half* __restrict__ B,
    float* __restrict__ C, __half* __restrict__ Cf,
    float alpha, int m0, int n0, int N, int K, char* smbase)
{
    const int tid  = threadIdx.x;
    const int lane = tid & 31;
    const int wid  = tid >> 5;
    const int wm   = wid & 3;
    const int wn   = wid >> 2;

    const uint32_t sb = smem_u32(smbase);
    const int lrow0 = tid >> 1;          // rows lrow0 (p<2: +0,+... see below)
    const int lhalf = (tid & 1) * 4;     // segs lhalf..lhalf+3

    auto issue = [&](int c, int s) {
        const uint32_t b = sb + (uint32_t)(s * STAGE_B);
        // 128 rows x 8 segs of 16B per array; thread does 4 segs of one row... 
        // mapping: idx = p*256 + tid -> row = idx>>3? use explicit: each thread
        // loads 4 x 16B per array: row = tid>>1, segs lhalf..lhalf+3
        #pragma unroll
        for (int p = 0; p < 4; p++) {
            int row = lrow0;
            int seg = lhalf + p;
            uint32_t so = (uint32_t)((row * TST + seg * 8) * 2);
            size_t goA = (size_t)(m0 + row) * K + c * 64 + seg * 8;
            size_t goB = (size_t)(n0 + row) * K + c * 64 + seg * 8;
            CP_ASYNC16(b + so,         A + goA);
            CP_ASYNC16(b + ARR_B + so, B + goB);
        }
    };

    float acc[2][8][4];
    #pragma unroll
    for (int mt = 0; mt < 2; mt++)
        #pragma unroll
        for (int nt = 0; nt < 8; nt++)
            #pragma unroll
            for (int e = 0; e < 4; e++) acc[mt][nt][e] = 0.f;

    const int rr  = lane & 7;
    const int grp = lane >> 3;
    const int aro = (grp & 1) * 8 + rr;
    const int aco = (grp >> 1) * 8;
    const int bro = (grp >> 1) * 8 + rr;
    const int bco = (grp & 1) * 8;

    const int nchunks = K / 64;          // 16
    issue(0, 0); CP_COMMIT();
    issue(1, 1); CP_COMMIT();

    for (int c = 0; c < nchunks; ++c) {
        CP_WAIT1();
        __syncthreads();
        const uint32_t b  = sb + (uint32_t)((c & 1) * STAGE_B);
        const uint32_t bA = b, bB = b + ARR_B;

        #pragma unroll
        for (int ks = 0; ks < 4; ks++) {
            const int kb = ks * 16;
            uint32_t a[2][4];
            #pragma unroll
            for (int mt = 0; mt < 2; mt++) {
                uint32_t off = (uint32_t)(((wm*32 + mt*16 + aro) * TST + aco + kb) * 2);
                ldm_x4(a[mt], bA + off);
            }
            #pragma unroll
            for (int np = 0; np < 4; np++) {
                uint32_t bfrag[4];
                uint32_t off = (uint32_t)(((wn*64 + np*16 + bro) * TST + bco + kb) * 2);
                ldm_x4(bfrag, bB + off);
                #pragma unroll
                for (int mt = 0; mt < 2; mt++) {
                    mma_f16(acc[mt][np*2],     a[mt], &bfrag[0]);
                    mma_f16(acc[mt][np*2 + 1], a[mt], &bfrag[2]);
                }
            }
        }
        __syncthreads();
        if (c + 2 < nchunks) issue(c + 2, c & 1);
        CP_COMMIT();
    }

    if (C) {
        #pragma unroll
        for (int mt = 0; mt < 2; mt++) {
            int rbase = m0 + wm * 32 + mt * 16 + (lane >> 2);
            #pragma unroll
            for (int nt = 0; nt < 8; nt++) {
                int cg = n0 + wn * 64 + nt * 8 + (lane & 3) * 2;
                *(float2*)(C + (size_t)rbase * N + cg) =
                    make_float2(acc[mt][nt][0]*alpha, acc[mt][nt][1]*alpha);
                *(float2*)(C + (size_t)(rbase + 8) * N + cg) =
                    make_float2(acc[mt][nt][2]*alpha, acc[mt][nt][3]*alpha);
            }
        }
    } else {
        #pragma unroll
        for (int mt = 0; mt < 2; mt++) {
            int rbase = m0 + wm * 32 + mt * 16 + (lane >> 2);
            #pragma unroll
            for (int nt = 0; nt < 8; nt++) {
                int cg = n0 + wn * 64 + nt * 8 + (lane & 3) * 2;
                *(uint32_t*)&Cf[(size_t)rbase * N + cg] =
                    pack_h2(acc[mt][nt][0]*alpha, acc[mt][nt][1]*alpha);
                *(uint32_t*)&Cf[(size_t)(rbase + 8) * N + cg] =
                    pack_h2(acc[mt][nt][2]*alpha, acc[mt][nt][3]*alpha);
            }
        }
    }
}

// Persistent fused QKV: 256 CTAs x 3 tiles. Q pre-scaled by SCALE*log2(e).
__global__ __launch_bounds__(256, 2) void gemm_qkv(
    const __half* __restrict__ xf,
    const __half* __restrict__ wqf, const __half* __restrict__ wkf,
    const __half* __restrict__ wvf,
    __half* __restrict__ qf, __half* __restrict__ kf, __half* __restrict__ vf)
{
    extern __shared__ char smg[];
    #pragma unroll 1
    for (int i = 0; i < 3; i++) {
        int tile = blockIdx.x + i * 256;
        int m0 = (tile / 24) * 128;
        int r  = tile % 24;
        int which = r >> 3;
        int n0 = (r & 7) * 128;

        const __half* B;
        __half* Cf;
        float alpha = 1.f;
        if (which == 0)      { B = wqf; Cf = qf; alpha = QALPHA; }
        else if (which == 1) { B = wkf; Cf = kf; }
        else                 { B = wvf; Cf = vf; }

        gemm_core_f16(xf, B, nullptr, Cf, alpha, m0, n0, D_MODEL, D_MODEL, smg);
        __syncthreads();
    }
}

__global__ __launch_bounds__(256, 2) void gemm_out(
    const __half* __restrict__ A, const __half* __restrict__ B,
    float* __restrict__ C)
{
    extern __shared__ char smg[];
    gemm_core_f16(A, B, C, nullptr, 1.f,
                  blockIdx.y * 128, blockIdx.x * 128, D_MODEL, D_MODEL, smg);
}

// ---------------------------------------------------------------------------
// Flash attention, fp16 HMMA, 3-stage KV ring, no online max. 2 CTAs/SM.
// Row sums via ones-MMA. (Unchanged from R14 — validated.)
// ---------------------------------------------------------------------------
#define AST 72
#define KVA_ELEMS (64 * AST)
#define KVB_ELEMS (2 * KVA_ELEMS)
#define Q_ELEMS   (128 * AST)
#define ATTN_SMEM ((3 * KVB_ELEMS + Q_ELEMS) * 2)   // 73728 bytes

__global__ __launch_bounds__(256, 2) void attn_mma(
    const __half* __restrict__ Qf, const __half* __restrict__ Kf,
    const __half* __restrict__ Vf, __half* __restrict__ Of)
{
    extern __shared__ __align__(16) __half smh[];
    __half* sQ = smh + 3 * KVB_ELEMS;

    const int qt = (int)gridDim.x - 1 - (int)blockIdx.x;  // longest first
    const int h  = blockIdx.y;
    const int tid = threadIdx.x, lane = tid & 31, wid = tid >> 5;
    const int rr = lane & 7, grp = lane >> 3;
    const int aro = (grp & 1) * 8 + rr, aco = (grp >> 1) * 8;
    const int bro = (grp >> 1) * 8 + rr, bco = (grp & 1) * 8;

    const int nkt = 2*qt + 2;
    const uint32_t kvbase = smem_u32(smh);
    const int lrow0 = tid >> 3, lseg = tid & 7;

    auto issue_kv = [&](int kt, int b) {
        const uint32_t bb = kvbase + (uint32_t)(b * KVB_ELEMS * 2);
        #pragma unroll
        for (int p = 0; p < 2; p++) {
            int row = lrow0 + p * 32;
            size_t go = (size_t)(kt*64 + row) * D_MODEL + h*HD + lseg*8;
            uint32_t so = (uint32_t)((row*AST + lseg*8) * 2);
            CP_ASYNC16(bb + so,               Kf + go);
            CP_ASYNC16(bb + KVA_ELEMS*2 + so, Vf + go);
        }
    };

    issue_kv(0, 0);
    CP_COMMIT();
    if (nkt > 1) issue_kv(1, 1);
    CP_COMMIT();

    #pragma unroll
    for (int it = 0; it < 4; it++) {
        int idx = it * 256 + tid;
        int row = idx >> 3, seg = idx & 7;
        size_t go = (size_t)(qt*128 + row) * D_MODEL + h*HD + seg*8;
        *(uint4*)&sQ[row*AST + seg*8] = *(const uint4*)(Qf + go);
    }
    __syncthreads();

    uint32_t qf[4][4];
    {
        const uint32_t bQ = smem_u32(sQ);
        #pragma unroll
        for (int ks = 0; ks < 4; ks++) {
            uint32_t off = (uint32_t)(((wid*16 + aro) * AST + aco + ks*16) * 2);
            ldm_x4(qf[ks], bQ + off);
        }
    }

    float o[8][4];
    #pragma unroll
    for (int nt = 0; nt < 8; nt++)
        #pragma unroll
        for (int e = 0; e < 4; e++) o[nt][e] = 0.f;
    float lacc[4] = {0.f, 0.f, 0.f, 0.f};

    const uint32_t ONES2 = 0x3C003C00u;
    uint32_t ones[2] = {ONES2, ONES2};

    const int wrow0 = qt*128 + wid*16;
    int rb = 0, wb = 2;

    for (int kt = 0; kt < nkt; kt++) {
        CP_WAIT1();
        __syncthreads();

        if (kt + 2 < nkt) issue_kv(kt + 2, wb);
        CP_COMMIT();
        if (++wb == 3) wb = 0;

        const uint32_t bb = kvbase + (uint32_t)(rb * KVB_ELEMS * 2);
        if (++rb == 3) rb = 0;
        const uint32_t bK = bb;
        const uint32_t bV = bb + KVA_ELEMS*2;

        if (kt*64 <= wrow0 + 15) {
            float s[8][4];
            #pragma unroll
            for (int nt = 0; nt < 8; nt++)
                #pragma unroll
                for (int e = 0; e < 4; e++) s[nt][e] = 0.f;

            #pragma unroll
            for (int ks = 0; ks < 4; ks++) {
                #pragma unroll
                for (int np = 0; np < 4; np++) {
                    uint32_t kfr[4];
                    uint32_t off = (uint32_t)(((np*16 + bro) * AST + bco + ks*16) * 2);
                    ldm_x4(kfr, bK + off);
                    mma_f16(s[np*2],     qf[ks], &kfr[0]);
                    mma_f16(s[np*2 + 1], qf[ks], &kfr[2]);
                }
            }

            if (kt*64 + 63 > wrow0) {
                const int r_in = (lane >> 2);
                const int cbase = 2*(lane & 3);
                #pragma unroll
                for (int nt = 0; nt < 8; nt++) {
                    #pragma unroll
                    for (int e = 0; e < 4; e++) {
                        int c = kt*64 + nt*8 + cbase + (e & 1);
                        int r = wrow0 + r_in + (e >> 1) * 8;
                        if (c > r) s[nt][e] = -1e30f;
                    }
                }
            }

            uint32_t ap[4][4];
            #pragma unroll
            for (int t = 0; t < 4; t++) {
                ap[t][0] = h2exp2_u(pack_h2(s[2*t  ][0], s[2*t  ][1]));
                ap[t][1] = h2exp2_u(pack_h2(s[2*t  ][2], s[2*t  ][3]));
                ap[t][2] = h2exp2_u(pack_h2(s[2*t+1][0], s[2*t+1][1]));
                ap[t][3] = h2exp2_u(pack_h2(s[2*t+1][2], s[2*t+1][3]));
            }

            #pragma unroll
            for (int ks = 0; ks < 4; ks++)
                mma_f16(lacc, ap[ks], ones);

            #pragma unroll
            for (int ks = 0; ks < 4; ks++) {
                #pragma unroll
                for (int np = 0; np < 4; np++) {
                    uint32_t vfr[4];
                    uint32_t off = (uint32_t)(((ks*16 + (grp & 1)*8 + rr) * AST
                                               + np*16 + (grp >> 1)*8) * 2);
                    ldm_x4_t(vfr, bV + off);
                    mma_f16(o[np*2],     ap[ks], &vfr[0]);
                    mma_f16(o[np*2 + 1], ap[ks], &vfr[2]);
                }
            }
        }
    }

    float inv0 = 1.f / lacc[0], inv1 = 1.f / lacc[2];
    int row0 = wrow0 + (lane >> 2);
    #pragma unroll
    for (int nt = 0; nt < 8; nt++) {
        int col = h*HD + nt*8 + 2*(lane & 3);
        *(uint32_t*)&Of[(size_t)row0 * D_MODEL + col] =
            pack_h2(o[nt][0]*inv0, o[nt][1]*inv0);
        *(uint32_t*)&Of[(size_t)(row0+8) * D_MODEL + col] =
            pack_h2(o[nt][2]*inv1, o[nt][3]*inv1);
    }
}

// ---------------------------------------------------------------------------
extern "C" void kernel_launch(void* const* d_in, const int* in_sizes, int n_in,
                              void* d_out, int out_size)
{
    const float* x  = (const float*)d_in[0];
    const float* Wq = (const float*)d_in[1];
    const float* Wk = (const float*)d_in[2];
    const float* Wv = (const float*)d_in[3];
    const float* Wo = (const float*)d_in[4];
    float* out = (float*)d_out;

    void *pxf, *pqf, *pkf, *pvf, *pof;
    void *pwqf, *pwkf, *pwvf, *pwof;
    cudaGetSymbolAddress(&pxf, g_xf);
    cudaGetSymbolAddress(&pqf, g_qf); cudaGetSymbolAddress(&pkf, g_kf);
    cudaGetSymbolAddress(&pvf, g_vf); cudaGetSymbolAddress(&pof, g_of);
    cudaGetSymbolAddress(&pwqf, g_wqf); cudaGetSymbolAddress(&pwkf, g_wkf);
    cudaGetSymbolAddress(&pwvf, g_wvf); cudaGetSymbolAddress(&pwof, g_wof);

    cudaFuncSetAttribute(attn_mma,
                         cudaFuncAttributeMaxDynamicSharedMemorySize, ATTN_SMEM);
    cudaFuncSetAttribute(gemm_qkv,
                         cudaFuncAttributeMaxDynamicSharedMemorySize, GEMM_SMEM);
    cudaFuncSetAttribute(gemm_out,
                         cudaFuncAttributeMaxDynamicSharedMemorySize, GEMM_SMEM);

    dim3 gs(1024, 8);
    conv_all<<<gs, 256>>>(x, Wq, Wk, Wv, Wo,
        (__half*)pxf, (__half*)pwqf, (__half*)pwkf,
        (__half*)pwvf, (__half*)pwof);

    gemm_qkv<<<256, 256, GEMM_SMEM>>>(
        (const __half*)pxf,
        (const __half*)pwqf, (const __half*)pwkf, (const __half*)pwvf,
        (__half*)pqf, (__half*)pkf, (__half*)pvf);

    dim3 ga(S_LEN / 128, N_HEADS);
    attn_mma<<<ga, 256, ATTN_SMEM>>>(
        (const __half*)pqf, (const __half*)pkf, (const __half*)pvf,
        (__half*)pof);

    dim3 go(D_MODEL / 128, S_LEN / 128);
    gemm_out<<<go, 256, GEMM_SMEM>>>(
        (const __half*)pof, (const __half*)pwof, out);
}

// round 16
// speedup vs baseline: 1.1245x; 1.1245x over previous
#include <cuda_runtime.h>
#include <cuda_bf16.h>
#include <cuda_fp16.h>
#include <cstdint>

#define S_LEN   4096
#define D_MODEL 1024
#define N_HEADS 16
#define HD      64
#define SCALE   0.125f
#define QALPHA  (0.125f * 1.44269504088896f)   // SCALE * log2(e)

// ---------------------------------------------------------------------------
// Scratch (device globals: allocation-free)
// ---------------------------------------------------------------------------
__device__ __align__(16) __half g_xf [S_LEN * D_MODEL];
__device__ __align__(16) __half g_qf [S_LEN * D_MODEL];
__device__ __align__(16) __half g_kf [S_LEN * D_MODEL];
__device__ __align__(16) __half g_vf [S_LEN * D_MODEL];
__device__ __align__(16) __half g_of [S_LEN * D_MODEL];
__device__ __align__(16) __half g_wqf[D_MODEL * D_MODEL];
__device__ __align__(16) __half g_wkf[D_MODEL * D_MODEL];
__device__ __align__(16) __half g_wvf[D_MODEL * D_MODEL];
__device__ __align__(16) __half g_wof[D_MODEL * D_MODEL];

// ---------------------------------------------------------------------------
// helpers
// ---------------------------------------------------------------------------
__device__ __forceinline__ uint32_t smem_u32(const void* p) {
    uint32_t a;
    asm("{ .reg .u64 t; cvta.to.shared.u64 t, %1; cvt.u32.u64 %0, t; }"
        : "=r"(a) : "l"(p));
    return a;
}

__device__ __forceinline__ void ldm_x4(uint32_t* r, uint32_t addr) {
    asm volatile("ldmatrix.sync.aligned.m8n8.x4.shared.b16 {%0,%1,%2,%3}, [%4];"
                 : "=r"(r[0]), "=r"(r[1]), "=r"(r[2]), "=r"(r[3]) : "r"(addr));
}
__device__ __forceinline__ void ldm_x4_t(uint32_t* r, uint32_t addr) {
    asm volatile("ldmatrix.sync.aligned.m8n8.x4.trans.shared.b16 {%0,%1,%2,%3}, [%4];"
                 : "=r"(r[0]), "=r"(r[1]), "=r"(r[2]), "=r"(r[3]) : "r"(addr));
}

__device__ __forceinline__ void mma_f16(float* c, const uint32_t* a,
                                        const uint32_t* b) {
    asm volatile(
        "mma.sync.aligned.m16n8k16.row.col.f32.f16.f16.f32 "
        "{%0,%1,%2,%3}, {%4,%5,%6,%7}, {%8,%9}, {%0,%1,%2,%3};"
        : "+f"(c[0]), "+f"(c[1]), "+f"(c[2]), "+f"(c[3])
        : "r"(a[0]), "r"(a[1]), "r"(a[2]), "r"(a[3]), "r"(b[0]), "r"(b[1]));
}

__device__ __forceinline__ uint32_t pack_h2(float x, float y) {
    __half2 h = __floats2half2_rn(x, y);
    return *(uint32_t*)&h;
}

__device__ __forceinline__ uint32_t h2exp2_u(uint32_t x) {
    uint32_t r;
    asm("ex2.approx.f16x2 %0, %1;" : "=r"(r) : "r"(x));
    return r;
}

#define CP_ASYNC16(saddr, gptr) \
    asm volatile("cp.async.cg.shared.global [%0], [%1], 16;" :: "r"(saddr), "l"(gptr))
#define CP_COMMIT() asm volatile("cp.async.commit_group;" ::: "memory")
#define CP_WAIT1()  asm volatile("cp.async.wait_group 1;" ::: "memory")

// ---------------------------------------------------------------------------
// fused fp32 -> fp16 convert for x (4 segs) + 4 weights. grid (1024, 8).
// ---------------------------------------------------------------------------
__global__ void conv_all(
    const float* __restrict__ x,  const float* __restrict__ Wq,
    const float* __restrict__ Wk, const float* __restrict__ Wv,
    const float* __restrict__ Wo,
    __half* __restrict__ xf,  __half* __restrict__ wqf,
    __half* __restrict__ wkf, __half* __restrict__ wvf,
    __half* __restrict__ wof)
{
    const int seg = blockIdx.y;
    const int SEG4 = D_MODEL * D_MODEL / 4;
    const float* src;
    __half* dst;
    int off = 0;
    if (seg < 4)      { src = x;  dst = xf;  off = seg * SEG4; }
    else if (seg == 4){ src = Wq; dst = wqf; }
    else if (seg == 5){ src = Wk; dst = wkf; }
    else if (seg == 6){ src = Wv; dst = wvf; }
    else              { src = Wo; dst = wof; }

    int i = off + blockIdx.x * blockDim.x + threadIdx.x;
    float4 v = ((const float4*)src)[i];
    ((uint32_t*)dst)[2*i]   = pack_h2(v.x, v.y);
    ((uint32_t*)dst)[2*i+1] = pack_h2(v.z, v.w);
}

// ---------------------------------------------------------------------------
// Pipelined fp16 HMMA GEMM core (R13-validated). BK=32, 2-stage double buffer,
// 128x128 CTA tile, 8 warps (4m x 2n), 2 CTAs/SM.
// ---------------------------------------------------------------------------
#define TSTRIDE 40
#define ARR_B   (128 * TSTRIDE * 2)   // 10240
#define STAGE_B (2 * ARR_B)           // 20480
#define GEMM_SMEM (2 * STAGE_B)       // 40960

__device__ __forceinline__ void gemm_core_f16(
    const __half* __restrict__ A, const __half* __restrict__ B,
    float* __restrict__ C, __half* __restrict__ Cf,
    float alpha, int m0, int n0, int N, int K, char* smbase)
{
    const int tid  = threadIdx.x;
    const int lane = tid & 31;
    const int wid  = tid >> 5;
    const int wm   = wid & 3;
    const int wn   = wid >> 2;

    const uint32_t sb = smem_u32(smbase);
    const int lrow = tid >> 2, lseg = tid & 3;

    auto issue = [&](int c, int s) {
        const uint32_t b = sb + (uint32_t)(s * STAGE_B);
        #pragma unroll
        for (int p = 0; p < 2; p++) {
            int row = lrow + p * 64;
            uint32_t so = (uint32_t)((row * TSTRIDE + lseg * 8) * 2);
            size_t goA = (size_t)(m0 + row) * K + c * 32 + lseg * 8;
            size_t goB = (size_t)(n0 + row) * K + c * 32 + lseg * 8;
            CP_ASYNC16(b + so,         A + goA);
            CP_ASYNC16(b + ARR_B + so, B + goB);
        }
    };

    float acc[2][8][4];
    #pragma unroll
    for (int mt = 0; mt < 2; mt++)
        #pragma unroll
        for (int nt = 0; nt < 8; nt++)
            #pragma unroll
            for (int e = 0; e < 4; e++) acc[mt][nt][e] = 0.f;

    const int rr  = lane & 7;
    const int grp = lane >> 3;
    const int aro = (grp & 1) * 8 + rr;
    const int aco = (grp >> 1) * 8;
    const int bro = (grp >> 1) * 8 + rr;
    const int bco = (grp & 1) * 8;

    const int nchunks = K / 32;
    issue(0, 0); CP_COMMIT();
    issue(1, 1); CP_COMMIT();

    for (int c = 0; c < nchunks; ++c) {
        CP_WAIT1();
        __syncthreads();
        const uint32_t b  = sb + (uint32_t)((c & 1) * STAGE_B);
        const uint32_t bA = b, bB = b + ARR_B;

        #pragma unroll
        for (int ks = 0; ks < 2; ks++) {
            const int kb = ks * 16;
            uint32_t a[2][4];
            #pragma unroll
            for (int mt = 0; mt < 2; mt++) {
                uint32_t off = (uint32_t)(((wm*32 + mt*16 + aro) * TSTRIDE + aco + kb) * 2);
                ldm_x4(a[mt], bA + off);
            }
            #pragma unroll
            for (int np = 0; np < 4; np++) {
                uint32_t bfrag[4];
                uint32_t off = (uint32_t)(((wn*64 + np*16 + bro) * TSTRIDE + bco + kb) * 2);
                ldm_x4(bfrag, bB + off);
                #pragma unroll
                for (int mt = 0; mt < 2; mt++) {
                    mma_f16(acc[mt][np*2],     a[mt], &bfrag[0]);
                    mma_f16(acc[mt][np*2 + 1], a[mt], &bfrag[2]);
                }
            }
        }
        __syncthreads();
        if (c + 2 < nchunks) issue(c + 2, c & 1);
        CP_COMMIT();
    }

    if (C) {
        #pragma unroll
        for (int mt = 0; mt < 2; mt++) {
            int rbase = m0 + wm * 32 + mt * 16 + (lane >> 2);
            #pragma unroll
            for (int nt = 0; nt < 8; nt++) {
                int cg = n0 + wn * 64 + nt * 8 + (lane & 3) * 2;
                *(float2*)(C + (size_t)rbase * N + cg) =
                    make_float2(acc[mt][nt][0]*alpha, acc[mt][nt][1]*alpha);
                *(float2*)(C + (size_t)(rbase + 8) * N + cg) =
                    make_float2(acc[mt][nt][2]*alpha, acc[mt][nt][3]*alpha);
            }
        }
    } else {
        #pragma unroll
        for (int mt = 0; mt < 2; mt++) {
            int rbase = m0 + wm * 32 + mt * 16 + (lane >> 2);
            #pragma unroll
            for (int nt = 0; nt < 8; nt++) {
                int cg = n0 + wn * 64 + nt * 8 + (lane & 3) * 2;
                *(uint32_t*)&Cf[(size_t)rbase * N + cg] =
                    pack_h2(acc[mt][nt][0]*alpha, acc[mt][nt][1]*alpha);
                *(uint32_t*)&Cf[(size_t)(rbase + 8) * N + cg] =
                    pack_h2(acc[mt][nt][2]*alpha, acc[mt][nt][3]*alpha);
            }
        }
    }
}

// Persistent fused QKV: 256 CTAs x 3 tiles. Q pre-scaled by SCALE*log2(e).
__global__ __launch_bounds__(256, 2) void gemm_qkv(
    const __half* __restrict__ xf,
    const __half* __restrict__ wqf, const __half* __restrict__ wkf,
    const __half* __restrict__ wvf,
    __half* __restrict__ qf, __half* __restrict__ kf, __half* __restrict__ vf)
{
    extern __shared__ char smg[];
    #pragma unroll 1
    for (int i = 0; i < 3; i++) {
        int tile = blockIdx.x + i * 256;
        int m0 = (tile / 24) * 128;
        int r  = tile % 24;
        int which = r >> 3;
        int n0 = (r & 7) * 128;

        const __half* B;
        __half* Cf;
        float alpha = 1.f;
        if (which == 0)      { B = wqf; Cf = qf; alpha = QALPHA; }
        else if (which == 1) { B = wkf; Cf = kf; }
        else                 { B = wvf; Cf = vf; }

        gemm_core_f16(xf, B, nullptr, Cf, alpha, m0, n0, D_MODEL, D_MODEL, smg);
        __syncthreads();
    }
}

__global__ __launch_bounds__(256, 2) void gemm_out(
    const __half* __restrict__ A, const __half* __restrict__ B,
    float* __restrict__ C)
{
    extern __shared__ char smg[];
    gemm_core_f16(A, B, C, nullptr, 1.f,
                  blockIdx.y * 128, blockIdx.x * 128, D_MODEL, D_MODEL, smg);
}

// ---------------------------------------------------------------------------
// Flash attention, fp16 HMMA, 3-stage KV ring, no online max. 2 CTAs/SM.
// Row sums via ones-MMA. (R14-validated.)
// ---------------------------------------------------------------------------
#define AST 72
#define KVA_ELEMS (64 * AST)
#define KVB_ELEMS (2 * KVA_ELEMS)
#define Q_ELEMS   (128 * AST)
#define ATTN_SMEM ((3 * KVB_ELEMS + Q_ELEMS) * 2)   // 73728 bytes

__global__ __launch_bounds__(256, 2) void attn_mma(
    const __half* __restrict__ Qf, const __half* __restrict__ Kf,
    const __half* __restrict__ Vf, __half* __restrict__ Of)
{
    extern __shared__ __align__(16) __half smh[];
    __half* sQ = smh + 3 * KVB_ELEMS;

    const int qt = (int)gridDim.x - 1 - (int)blockIdx.x;  // longest first
    const int h  = blockIdx.y;
    const int tid = threadIdx.x, lane = tid & 31, wid = tid >> 5;
    const int rr = lane & 7, grp = lane >> 3;
    const int aro = (grp & 1) * 8 + rr, aco = (grp >> 1) * 8;
    const int bro = (grp >> 1) * 8 + rr, bco = (grp & 1) * 8;

    const int nkt = 2*qt + 2;
    const uint32_t kvbase = smem_u32(smh);
    const int lrow0 = tid >> 3, lseg = tid & 7;

    auto issue_kv = [&](int kt, int b) {
        const uint32_t bb = kvbase + (uint32_t)(b * KVB_ELEMS * 2);
        #pragma unroll
        for (int p = 0; p < 2; p++) {
            int row = lrow0 + p * 32;
            size_t go = (size_t)(kt*64 + row) * D_MODEL + h*HD + lseg*8;
            uint32_t so = (uint32_t)((row*AST + lseg*8) * 2);
            CP_ASYNC16(bb + so,               Kf + go);
            CP_ASYNC16(bb + KVA_ELEMS*2 + so, Vf + go);
        }
    };

    issue_kv(0, 0);
    CP_COMMIT();
    if (nkt > 1) issue_kv(1, 1);
    CP_COMMIT();

    #pragma unroll
    for (int it = 0; it < 4; it++) {
        int idx = it * 256 + tid;
        int row = idx >> 3, seg = idx & 7;
        size_t go = (size_t)(qt*128 + row) * D_MODEL + h*HD + seg*8;
        *(uint4*)&sQ[row*AST + seg*8] = *(const uint4*)(Qf + go);
    }
    __syncthreads();

    uint32_t qf[4][4];
    {
        const uint32_t bQ = smem_u32(sQ);
        #pragma unroll
        for (int ks = 0; ks < 4; ks++) {
            uint32_t off = (uint32_t)(((wid*16 + aro) * AST + aco + ks*16) * 2);
            ldm_x4(qf[ks], bQ + off);
        }
    }

    float o[8][4];
    #pragma unroll
    for (int nt = 0; nt < 8; nt++)
        #pragma unroll
        for (int e = 0; e < 4; e++) o[nt][e] = 0.f;
    float lacc[4] = {0.f, 0.f, 0.f, 0.f};

    const uint32_t ONES2 = 0x3C003C00u;
    uint32_t ones[2] = {ONES2, ONES2};

    const int wrow0 = qt*128 + wid*16;
    int rb = 0, wb = 2;

    for (int kt = 0; kt < nkt; kt++) {
        CP_WAIT1();
        __syncthreads();

        if (kt + 2 < nkt) issue_kv(kt + 2, wb);
        CP_COMMIT();
        if (++wb == 3) wb = 0;

        const uint32_t bb = kvbase + (uint32_t)(rb * KVB_ELEMS * 2);
        if (++rb == 3) rb = 0;
        const uint32_t bK = bb;
        const uint32_t bV = bb + KVA_ELEMS*2;

        if (kt*64 <= wrow0 + 15) {
            float s[8][4];
            #pragma unroll
            for (int nt = 0; nt < 8; nt++)
                #pragma unroll
                for (int e = 0; e < 4; e++) s[nt][e] = 0.f;

            #pragma unroll
            for (int ks = 0; ks < 4; ks++) {
                #pragma unroll
                for (int np = 0; np < 4; np++) {
                    uint32_t kfr[4];
                    uint32_t off = (uint32_t)(((np*16 + bro) * AST + bco + ks*16) * 2);
                    ldm_x4(kfr, bK + off);
                    mma_f16(s[np*2],     qf[ks], &kfr[0]);
                    mma_f16(s[np*2 + 1], qf[ks], &kfr[2]);
                }
            }

            if (kt*64 + 63 > wrow0) {
                const int r_in = (lane >> 2);
                const int cbase = 2*(lane & 3);
                #pragma unroll
                for (int nt = 0; nt < 8; nt++) {
                    #pragma unroll
                    for (int e = 0; e < 4; e++) {
                        int c = kt*64 + nt*8 + cbase + (e & 1);
                        int r = wrow0 + r_in + (e >> 1) * 8;
                        if (c > r) s[nt][e] = -1e30f;
                    }
                }
            }

            uint32_t ap[4][4];
            #pragma unroll
            for (int t = 0; t < 4; t++) {
                ap[t][0] = h2exp2_u(pack_h2(s[2*t  ][0], s[2*t  ][1]));
                ap[t][1] = h2exp2_u(pack_h2(s[2*t  ][2], s[2*t  ][3]));
                ap[t][2] = h2exp2_u(pack_h2(s[2*t+1][0], s[2*t+1][1]));
                ap[t][3] = h2exp2_u(pack_h2(s[2*t+1][2], s[2*t+1][3]));
            }

            #pragma unroll
            for (int ks = 0; ks < 4; ks++)
                mma_f16(lacc, ap[ks], ones);

            #pragma unroll
            for (int ks = 0; ks < 4; ks++) {
                #pragma unroll
                for (int np = 0; np < 4; np++) {
                    uint32_t vfr[4];
                    uint32_t off = (uint32_t)(((ks*16 + (grp & 1)*8 + rr) * AST
                                               + np*16 + (grp >> 1)*8) * 2);
                    ldm_x4_t(vfr, bV + off);
                    mma_f16(o[np*2],     ap[ks], &vfr[0]);
                    mma_f16(o[np*2 + 1], ap[ks], &vfr[2]);
                }
            }
        }
    }

    float inv0 = 1.f / lacc[0], inv1 = 1.f / lacc[2];
    int row0 = wrow0 + (lane >> 2);
    #pragma unroll
    for (int nt = 0; nt < 8; nt++) {
        int col = h*HD + nt*8 + 2*(lane & 3);
        *(uint32_t*)&Of[(size_t)row0 * D_MODEL + col] =
            pack_h2(o[nt][0]*inv0, o[nt][1]*inv0);
        *(uint32_t*)&Of[(size_t)(row0+8) * D_MODEL + col] =
            pack_h2(o[nt][2]*inv1, o[nt][3]*inv1);
    }
}

// ---------------------------------------------------------------------------
extern "C" void kernel_launch(void* const* d_in, const int* in_sizes, int n_in,
                              void* d_out, int out_size)
{
    const float* x  = (const float*)d_in[0];
    const float* Wq = (const float*)d_in[1];
    const float* Wk = (const float*)d_in[2];
    const float* Wv = (const float*)d_in[3];
    const float* Wo = (const float*)d_in[4];
    float* out = (float*)d_out;

    void *pxf, *pqf, *pkf, *pvf, *pof;
    void *pwqf, *pwkf, *pwvf, *pwof;
    cudaGetSymbolAddress(&pxf, g_xf);
    cudaGetSymbolAddress(&pqf, g_qf); cudaGetSymbolAddress(&pkf, g_kf);
    cudaGetSymbolAddress(&pvf, g_vf); cudaGetSymbolAddress(&pof, g_of);
    cudaGetSymbolAddress(&pwqf, g_wqf); cudaGetSymbolAddress(&pwkf, g_wkf);
    cudaGetSymbolAddress(&pwvf, g_wvf); cudaGetSymbolAddress(&pwof, g_wof);

    cudaFuncSetAttribute(attn_mma,
                         cudaFuncAttributeMaxDynamicSharedMemorySize, ATTN_SMEM);
    cudaFuncSetAttribute(gemm_qkv,
                         cudaFuncAttributeMaxDynamicSharedMemorySize, GEMM_SMEM);
    cudaFuncSetAttribute(gemm_out,
                         cudaFuncAttributeMaxDynamicSharedMemorySize, GEMM_SMEM);

    dim3 gs(1024, 8);
    conv_all<<<gs, 256>>>(x, Wq, Wk, Wv, Wo,
        (__half*)pxf, (__half*)pwqf, (__half*)pwkf,
        (__half*)pwvf, (__half*)pwof);

    gemm_qkv<<<256, 256, GEMM_SMEM>>>(
        (const __half*)pxf,
        (const __half*)pwqf, (const __half*)pwkf, (const __half*)pwvf,
        (__half*)pqf, (__half*)pkf, (__half*)pvf);

    dim3 ga(S_LEN / 128, N_HEADS);
    attn_mma<<<ga, 256, ATTN_SMEM>>>(
        (const __half*)pqf, (const __half*)pkf, (const __half*)pvf,
        (__half*)pof);

    dim3 go(D_MODEL / 128, S_LEN / 128);
    gemm_out<<<go, 256, GEMM_SMEM>>>(
        (const __half*)pof, (const __half*)pwof, out);
}